// round 15
// baseline (speedup 1.0000x reference)
#include <cuda_runtime.h>
#include <cuda_fp16.h>
#include <cstdint>

// y = x @ W^T + bias, B=K=N=512 fp32.  LNS reference == plain fp32 matmul.
// Single-term fp16 HMMA (rel_err ~2.9e-4, budget 1e-3), fp32 accumulate.
// BM=BN=32 -> 256 CTAs, 2 CTAs/SM: co-resident CTAs overlap each other's
// prologue/LDG/barrier latency (the measured ~7us fixed cost).
// r14 bug fixed: producer now covers the FULL 128-float k-chunk per row
// (r<8, slots p_c+4r), previously only half was written.

constexpr int KDIM = 512;
constexpr int NDIM = 512;
constexpr int BDIM = 512;

constexpr int BM = 32;
constexpr int BN = 32;
constexpr int KC = 128;                  // k per chunk
constexpr int NCHUNK = KDIM / KC;        // 4
constexpr int NTH = 128;                 // 4 warps, 2x2 grid of 16x16 tiles

// smem row stride: 128 fp16 = 256B + 16B pad = 272B (68 words; 68 mod 32 = 4
// -> 8-row ldmatrix phases hit disjoint bank quads).
constexpr int ROWB = 272;
constexpr int A_OFF = 0;
constexpr int B_OFF = BM * ROWB;              // 8704
constexpr int STAGE = B_OFF + BN * ROWB;      // 17408
constexpr int SMEM_TOTAL = 2 * STAGE;         // 34816 (fits 2+ CTAs/SM)

__device__ __forceinline__ uint32_t smem_u32(const void* p) {
    uint32_t a;
    asm("{ .reg .u64 t; cvta.to.shared.u64 t, %1; cvt.u32.u64 %0, t; }"
        : "=r"(a) : "l"(p));
    return a;
}

__device__ __forceinline__ void ldsm_x4(uint32_t* r, uint32_t addr) {
    asm volatile("ldmatrix.sync.aligned.m8n8.x4.shared.b16 {%0,%1,%2,%3}, [%4];"
                 : "=r"(r[0]), "=r"(r[1]), "=r"(r[2]), "=r"(r[3]) : "r"(addr));
}

__device__ __forceinline__ void mma16816(float* c, const uint32_t* a,
                                         uint32_t b0, uint32_t b1) {
    asm volatile(
        "mma.sync.aligned.m16n8k16.row.col.f32.f16.f16.f32 "
        "{%0,%1,%2,%3}, {%4,%5,%6,%7}, {%8,%9}, {%0,%1,%2,%3};"
        : "+f"(c[0]), "+f"(c[1]), "+f"(c[2]), "+f"(c[3])
        : "r"(a[0]), "r"(a[1]), "r"(a[2]), "r"(a[3]), "r"(b0), "r"(b1));
}

// float4 -> 4 fp16 (8 bytes) store.
__device__ __forceinline__ void cvt_sts(char* smem, uint32_t byte_off, float4 v) {
    __half2 h0 = __floats2half2_rn(v.x, v.y);
    __half2 h1 = __floats2half2_rn(v.z, v.w);
    *reinterpret_cast<uint2*>(smem + byte_off) =
        make_uint2(*reinterpret_cast<uint32_t*>(&h0),
                   *reinterpret_cast<uint32_t*>(&h1));
}

__global__ __launch_bounds__(NTH, 2)
void lns_linear_kernel(const float* __restrict__ X,
                       const float* __restrict__ W,
                       const float* __restrict__ bias,
                       float* __restrict__ Y)
{
    extern __shared__ char smem[];
    const uint32_t sb = smem_u32(smem);
    const int tid = threadIdx.x;
    const int wid = tid >> 5;
    const int lid = tid & 31;
    const int wm = wid >> 1;              // 0..1  (m tile of 16)
    const int wn = wid & 1;               // 0..1  (n tile of 16)
    const int block_m = blockIdx.y * BM;
    const int block_n = blockIdx.x * BN;

    // producer mapping (per chunk = 32x128 A f32, 32x128 B f32):
    // row = tid>>2 (0..31); 4 threads/row; float4 slot = (tid&3) + 4r, r=0..7
    // -> 8 float4 per thread per matrix = full 128 floats per row.
    const int p_row = tid >> 2, p_c = tid & 3;
    const float* Aptr = X + (block_m + p_row) * KDIM + p_c * 4;
    const float* Bptr = W + (block_n + p_row) * KDIM + p_c * 4;
    const uint32_t p_st = (uint32_t)(p_row * ROWB + p_c * 8);   // +32B per r

    // ldmatrix lane addressing (byte offsets within tile)
    const uint32_t a_ld = (uint32_t)((wm * 16 + (lid & 15)) * ROWB + (lid >> 4) * 16);
    const uint32_t b_ld = (uint32_t)((wn * 16 + ((lid & 7) | ((lid >> 4) << 3))) * ROWB
                                     + (((lid >> 3) & 1) * 16));

    // 4 independent accumulator chains: {even,odd k-step} x {n8 block 0,1}
    float c0[2][4] = {};
    float c1[2][4] = {};

    float4 pa[8], pb[8];
    #pragma unroll
    for (int r = 0; r < 8; ++r) {
        pa[r] = *reinterpret_cast<const float4*>(Aptr + r * 16);
        pb[r] = *reinterpret_cast<const float4*>(Bptr + r * 16);
    }

    for (int i = 0; i < NCHUNK; ++i) {
        char* buf = smem + (i & 1) * STAGE;
        const uint32_t bufb = sb + (i & 1) * STAGE;

        // commit prefetched chunk (cvt f32 -> fp16); full 256B per row
        #pragma unroll
        for (int r = 0; r < 8; ++r) {
            cvt_sts(buf, A_OFF + p_st + r * 32, pa[r]);
            cvt_sts(buf, B_OFF + p_st + r * 32, pb[r]);
        }
        __syncthreads();
        // (single sync per chunk is safe: writes to buffer b in iter i+1 only
        //  happen after sync(i), by which point every warp has finished the
        //  iter i-1 compute that read buffer b.)

        if (i + 1 < NCHUNK) {
            const int off = (i + 1) * KC;
            #pragma unroll
            for (int r = 0; r < 8; ++r) {
                pa[r] = *reinterpret_cast<const float4*>(Aptr + off + r * 16);
                pb[r] = *reinterpret_cast<const float4*>(Bptr + off + r * 16);
            }
        }

        #pragma unroll
        for (int s = 0; s < KC / 16; ++s) {
            const int p = s & 1;
            uint32_t a[4], b[4];
            ldsm_x4(a, bufb + A_OFF + a_ld + s * 32);
            ldsm_x4(b, bufb + B_OFF + b_ld + s * 32);
            mma16816(c0[p], a, b[0], b[1]);
            mma16816(c1[p], a, b[2], b[3]);
        }
    }

    // epilogue: merge chains, add bias, store
    const int row0 = block_m + wm * 16 + (lid >> 2);
    const int coln = block_n + wn * 16 + 2 * (lid & 3);
    float f0[4], f1[4];
    #pragma unroll
    for (int j = 0; j < 4; ++j) {
        f0[j] = c0[0][j] + c0[1][j];
        f1[j] = c1[0][j] + c1[1][j];
    }
    #pragma unroll
    for (int j = 0; j < 2; ++j) {
        const float* cc = j ? f1 : f0;
        const int n = coln + j * 8;
        float2 bv = *reinterpret_cast<const float2*>(bias + n);
        *reinterpret_cast<float2*>(Y + row0 * NDIM + n) =
            make_float2(cc[0] + bv.x, cc[1] + bv.y);
        *reinterpret_cast<float2*>(Y + (row0 + 8) * NDIM + n) =
            make_float2(cc[2] + bv.x, cc[3] + bv.y);
    }
}

extern "C" void kernel_launch(void* const* d_in, const int* in_sizes, int n_in,
                              void* d_out, int out_size)
{
    const float* x    = (const float*)d_in[0];   // [512, 512]
    const float* w    = (const float*)d_in[1];   // [512, 512] (N, K)
    const float* bias = (const float*)d_in[2];   // [512]
    float* y = (float*)d_out;                    // [512, 512]

    cudaFuncSetAttribute(lns_linear_kernel,
                         cudaFuncAttributeMaxDynamicSharedMemorySize, SMEM_TOTAL);
    dim3 grid(NDIM / BN, BDIM / BM);             // (16, 16) = 256 CTAs, 2/SM
    lns_linear_kernel<<<grid, NTH, SMEM_TOTAL>>>(x, w, bias, y);
}

// round 16
// speedup vs baseline: 1.2177x; 1.2177x over previous
#include <cuda_runtime.h>
#include <cuda_fp16.h>
#include <cstdint>

// y = x @ W^T + bias, B=K=N=512 fp32.  LNS reference == plain fp32 matmul.
// Single-term fp16 HMMA (rel_err ~2.9e-4, budget 1e-3), fp32 accumulate.
// SINGLE-PHASE kernel: the entire K=512 tile (A 64x512, B 32x512 fp16,
// ~100KB smem) is loaded in ONE wave of independent LDGs (MLP~48/thread),
// converted and stored, then ONE __syncthreads, then 32 uninterrupted
// k-steps of ldsm+mma. No double buffer, no per-chunk barriers: the
// serialized 4-chunk pipeline skeleton (the measured ~12K-cycle fixed
// cost) is collapsed into one load wave + one compute run.

constexpr int KDIM = 512;
constexpr int NDIM = 512;
constexpr int BDIM = 512;

constexpr int BM = 64;
constexpr int BN = 32;
constexpr int NTH = 256;                 // 8 warps, 4x2 grid of 16x16 tiles

// smem row: 512 fp16 = 1024B + 16B pad = 1040B (260 words; 260 mod 32 = 4
// -> 8-row ldmatrix phases hit disjoint bank quads).
constexpr int ROWB = 1040;
constexpr int A_OFF = 0;
constexpr int B_OFF = BM * ROWB;              // 66560
constexpr int SMEM_TOTAL = B_OFF + BN * ROWB; // 99840 (1 CTA/SM)

__device__ __forceinline__ uint32_t smem_u32(const void* p) {
    uint32_t a;
    asm("{ .reg .u64 t; cvta.to.shared.u64 t, %1; cvt.u32.u64 %0, t; }"
        : "=r"(a) : "l"(p));
    return a;
}

__device__ __forceinline__ void ldsm_x4(uint32_t* r, uint32_t addr) {
    asm volatile("ldmatrix.sync.aligned.m8n8.x4.shared.b16 {%0,%1,%2,%3}, [%4];"
                 : "=r"(r[0]), "=r"(r[1]), "=r"(r[2]), "=r"(r[3]) : "r"(addr));
}

__device__ __forceinline__ void mma16816(float* c, const uint32_t* a,
                                         uint32_t b0, uint32_t b1) {
    asm volatile(
        "mma.sync.aligned.m16n8k16.row.col.f32.f16.f16.f32 "
        "{%0,%1,%2,%3}, {%4,%5,%6,%7}, {%8,%9}, {%0,%1,%2,%3};"
        : "+f"(c[0]), "+f"(c[1]), "+f"(c[2]), "+f"(c[3])
        : "r"(a[0]), "r"(a[1]), "r"(a[2]), "r"(a[3]), "r"(b0), "r"(b1));
}

// float4 -> 4 fp16 (8 bytes) store.
__device__ __forceinline__ void cvt_sts(char* smem, uint32_t byte_off, float4 v) {
    __half2 h0 = __floats2half2_rn(v.x, v.y);
    __half2 h1 = __floats2half2_rn(v.z, v.w);
    *reinterpret_cast<uint2*>(smem + byte_off) =
        make_uint2(*reinterpret_cast<uint32_t*>(&h0),
                   *reinterpret_cast<uint32_t*>(&h1));
}

__global__ __launch_bounds__(NTH, 1)
void lns_linear_kernel(const float* __restrict__ X,
                       const float* __restrict__ W,
                       const float* __restrict__ bias,
                       float* __restrict__ Y)
{
    extern __shared__ char smem[];
    const uint32_t sb = smem_u32(smem);
    const int tid = threadIdx.x;
    const int wid = tid >> 5;
    const int lid = tid & 31;
    const int wm = wid >> 1;              // 0..3  (m tile of 16)
    const int wn = wid & 1;               // 0..1  (n tile of 16)
    const int block_m = blockIdx.y * BM;
    const int block_n = blockIdx.x * BN;

    // ---- single-phase producer: full K=512 ----
    // A: 64 rows x 128 float4; 4 threads/row -> 32 float4/thread.
    // B: 32 rows x 128 float4; 8 threads/row -> 16 float4/thread.
    {
        const int a_row = tid >> 2, a_c = tid & 3;
        const float* Aptr = X + (block_m + a_row) * KDIM + a_c * 4;
        const uint32_t a_st = (uint32_t)(a_row * ROWB + a_c * 8);   // +32B per slot
        #pragma unroll
        for (int r = 0; r < 32; ++r) {
            float4 v = *reinterpret_cast<const float4*>(Aptr + r * 16);
            cvt_sts(smem, A_OFF + a_st + r * 32, v);
        }
        const int b_row = tid >> 3, b_c = tid & 7;
        const float* Bptr = W + (block_n + b_row) * KDIM + b_c * 4;
        const uint32_t b_st = (uint32_t)(b_row * ROWB + b_c * 8);   // +64B per slot
        #pragma unroll
        for (int r = 0; r < 16; ++r) {
            float4 v = *reinterpret_cast<const float4*>(Bptr + r * 32);
            cvt_sts(smem, B_OFF + b_st + r * 64, v);
        }
    }
    __syncthreads();   // the ONLY barrier

    // ---- ldmatrix lane addressing (byte offsets within tile) ----
    const uint32_t a_ld = (uint32_t)((wm * 16 + (lid & 15)) * ROWB + (lid >> 4) * 16);
    const uint32_t b_ld = (uint32_t)((wn * 16 + ((lid & 7) | ((lid >> 4) << 3))) * ROWB
                                     + (((lid >> 3) & 1) * 16));

    // 4 independent accumulator chains: {even,odd k-step} x {n8 block 0,1}
    float c0[2][4] = {};
    float c1[2][4] = {};

    #pragma unroll
    for (int s = 0; s < KDIM / 16; ++s) {   // 32 k-steps, no barriers
        const int p = s & 1;
        uint32_t a[4], b[4];
        ldsm_x4(a, sb + A_OFF + a_ld + s * 32);
        ldsm_x4(b, sb + B_OFF + b_ld + s * 32);
        mma16816(c0[p], a, b[0], b[1]);
        mma16816(c1[p], a, b[2], b[3]);
    }

    // ---- epilogue: merge chains, add bias, store ----
    const int row0 = block_m + wm * 16 + (lid >> 2);
    const int coln = block_n + wn * 16 + 2 * (lid & 3);
    float f0[4], f1[4];
    #pragma unroll
    for (int j = 0; j < 4; ++j) {
        f0[j] = c0[0][j] + c0[1][j];
        f1[j] = c1[0][j] + c1[1][j];
    }
    #pragma unroll
    for (int j = 0; j < 2; ++j) {
        const float* cc = j ? f1 : f0;
        const int n = coln + j * 8;
        float2 bv = *reinterpret_cast<const float2*>(bias + n);
        *reinterpret_cast<float2*>(Y + row0 * NDIM + n) =
            make_float2(cc[0] + bv.x, cc[1] + bv.y);
        *reinterpret_cast<float2*>(Y + (row0 + 8) * NDIM + n) =
            make_float2(cc[2] + bv.x, cc[3] + bv.y);
    }
}

extern "C" void kernel_launch(void* const* d_in, const int* in_sizes, int n_in,
                              void* d_out, int out_size)
{
    const float* x    = (const float*)d_in[0];   // [512, 512]
    const float* w    = (const float*)d_in[1];   // [512, 512] (N, K)
    const float* bias = (const float*)d_in[2];   // [512]
    float* y = (float*)d_out;                    // [512, 512]

    cudaFuncSetAttribute(lns_linear_kernel,
                         cudaFuncAttributeMaxDynamicSharedMemorySize, SMEM_TOTAL);
    dim3 grid(NDIM / BN, BDIM / BM);             // (16, 8) = 128 CTAs, one wave
    lns_linear_kernel<<<grid, NTH, SMEM_TOTAL>>>(x, w, bias, y);
}